// round 3
// baseline (speedup 1.0000x reference)
#include <cuda_runtime.h>
#include <math.h>

#define BB 4096
#define GG 512
#define DD 64
#define PP (GG * DD)     // 32768 features per row
#define GT 64            // groups per k1 block
#define RT 16            // rows per k1 block
#define NBCH 16          // batch chunks for partial BN stats
#define NGCH 16          // group chunks for partial BN stats

// ---- device scratch (no allocations allowed) ----
__device__ __align__(16) float g_reps[(size_t)BB * GG];   // 8 MiB
__device__ float g_psum[NBCH * GG];
__device__ float g_psq[NBCH * GG];
__device__ __align__(16) float g_c[GG];
__device__ float g_K;

// ---------------------------------------------------------------------------
// k1: reps[b,g] = leaky_relu( sum_d x[b, idx[g,d]] * W[g,d] )
// Block tile: GT=64 groups x RT=16 rows. idx+W staged in smem; reps staged in
// smem and written coalesced. One warp per (b,g) dot product.
// ---------------------------------------------------------------------------
__global__ __launch_bounds__(256) void k1_reps(const float* __restrict__ x,
                                               const void* __restrict__ idx_raw,
                                               const float* __restrict__ W) {
    __shared__ int   sIdx[GT * DD];    // 16 KiB
    __shared__ float sW[GT * DD];      // 16 KiB
    __shared__ float sReps[RT * GT];   // 4 KiB

    const int g0 = blockIdx.x * GT;
    const int b0 = blockIdx.y * RT;
    const int tid = threadIdx.x;

    // Detect idx element width. jax with x64 enabled gives int64 (little-endian:
    // every high word is 0 for these small indices); x64 disabled gives int32.
    const int* r32 = (const int*)idx_raw;
    const bool is64 = (r32[1] == 0) && (r32[3] == 0) && (r32[5] == 0);

    for (int j = tid; j < GT * DD; j += 256) {
        long long v;
        if (is64) v = ((const long long*)idx_raw)[(size_t)g0 * DD + j];
        else      v = ((const int*)idx_raw)[(size_t)g0 * DD + j];
        sIdx[j] = (int)v;
        sW[j]   = W[(size_t)g0 * DD + j];
    }
    __syncthreads();

    const int warp = tid >> 5;
    const int lane = tid & 31;

    // 64*16 = 1024 warp-tasks, 8 warps -> 128 iterations each
    for (int t = warp; t < GT * RT; t += 8) {
        const int g = t & (GT - 1);
        const int r = t >> 6;
        const float* xrow = x + (size_t)(b0 + r) * PP;
        const int base = (g << 6) + lane;
        float acc = xrow[sIdx[base]]      * sW[base]
                  + xrow[sIdx[base + 32]] * sW[base + 32];
        acc += __shfl_down_sync(0xffffffffu, acc, 16);
        acc += __shfl_down_sync(0xffffffffu, acc, 8);
        acc += __shfl_down_sync(0xffffffffu, acc, 4);
        acc += __shfl_down_sync(0xffffffffu, acc, 2);
        acc += __shfl_down_sync(0xffffffffu, acc, 1);
        if (lane == 0) {
            sReps[(r << 6) + g] = (acc >= 0.0f) ? acc : 0.2f * acc;
        }
    }
    __syncthreads();

    for (int j = tid; j < RT * GT; j += 256) {
        const int r = j >> 6;
        const int g = j & 63;
        g_reps[(size_t)(b0 + r) * GG + g0 + g] = sReps[j];
    }
}

// ---------------------------------------------------------------------------
// k2a: deterministic partial BN stats. Block = (32 groups x 256 rows).
// Thread layout: lane = group (coalesced 128B reads), warp-row = batch row.
// ---------------------------------------------------------------------------
__global__ __launch_bounds__(256) void k2a_stats() {
    const int g0 = blockIdx.x * 32;
    const int b0 = blockIdx.y * (BB / NBCH);   // 256 rows
    const int tid = threadIdx.x;
    const int gi = tid & 31;
    const int ri = tid >> 5;   // 0..7

    float s = 0.0f, s2 = 0.0f;
    #pragma unroll 4
    for (int i = 0; i < 32; i++) {
        float v = g_reps[(size_t)(b0 + i * 8 + ri) * GG + g0 + gi];
        s += v;
        s2 += v * v;
    }
    __shared__ float shs[8][33];
    __shared__ float shq[8][33];
    shs[ri][gi] = s;
    shq[ri][gi] = s2;
    __syncthreads();
    if (tid < 32) {
        float ts = 0.0f, t2 = 0.0f;
        #pragma unroll
        for (int r = 0; r < 8; r++) { ts += shs[r][tid]; t2 += shq[r][tid]; }
        g_psum[blockIdx.y * GG + g0 + tid] = ts;
        g_psq[blockIdx.y * GG + g0 + tid]  = t2;
    }
}

// ---------------------------------------------------------------------------
// k2b: finalize. c[g] = fc_w*gamma*rstd ;  K = fc_b + sum fc_w*(beta - gamma*mean*rstd)
// ---------------------------------------------------------------------------
__global__ __launch_bounds__(GG) void k2b_finalize(const float* __restrict__ gamma,
                                                   const float* __restrict__ beta,
                                                   const float* __restrict__ fcw,
                                                   const float* __restrict__ fcb) {
    const int g = threadIdx.x;
    float s = 0.0f, s2 = 0.0f;
    #pragma unroll
    for (int i = 0; i < NBCH; i++) {
        s  += g_psum[i * GG + g];
        s2 += g_psq[i * GG + g];
    }
    const float inv_b = 1.0f / (float)BB;
    const float mean = s * inv_b;
    const float var = s2 * inv_b - mean * mean;
    const float rstd = rsqrtf(var + 1e-5f);
    const float cg = fcw[g] * gamma[g] * rstd;
    g_c[g] = cg;
    float kterm = fcw[g] * beta[g] - cg * mean;

    __shared__ float sh[GG];
    sh[g] = kterm;
    __syncthreads();
    for (int off = GG / 2; off >= 1; off >>= 1) {
        if (g < off) sh[g] += sh[g + off];
        __syncthreads();
    }
    if (g == 0) g_K = sh[0] + fcb[0];
}

// ---------------------------------------------------------------------------
// k3: out[b] = sigmoid( dot(reps[b,:], c) + K ).  One warp per row, float4.
// ---------------------------------------------------------------------------
__global__ __launch_bounds__(256) void k3_out(float* __restrict__ out) {
    const int gw = (blockIdx.x * blockDim.x + threadIdx.x) >> 5;
    const int lane = threadIdx.x & 31;
    if (gw >= BB) return;

    const float4* row = (const float4*)(g_reps + (size_t)gw * GG);
    const float4* c4 = (const float4*)g_c;
    float acc = 0.0f;
    #pragma unroll
    for (int k = 0; k < 4; k++) {
        float4 a = row[lane + 32 * k];
        float4 b = c4[lane + 32 * k];
        acc += a.x * b.x + a.y * b.y + a.z * b.z + a.w * b.w;
    }
    acc += __shfl_down_sync(0xffffffffu, acc, 16);
    acc += __shfl_down_sync(0xffffffffu, acc, 8);
    acc += __shfl_down_sync(0xffffffffu, acc, 4);
    acc += __shfl_down_sync(0xffffffffu, acc, 2);
    acc += __shfl_down_sync(0xffffffffu, acc, 1);
    if (lane == 0) {
        float l = acc + g_K;
        out[gw] = 1.0f / (1.0f + expf(-l));
    }
}

// ---------------------------------------------------------------------------
extern "C" void kernel_launch(void* const* d_in, const int* in_sizes, int n_in,
                              void* d_out, int out_size) {
    const float* x     = (const float*)d_in[0];
    const void*  idx   = d_in[1];
    const float* W     = (const float*)d_in[2];
    const float* gamma = (const float*)d_in[3];
    const float* beta  = (const float*)d_in[4];
    const float* fcw   = (const float*)d_in[5];
    const float* fcb   = (const float*)d_in[6];
    float* out = (float*)d_out;

    k1_reps<<<dim3(GG / GT, BB / RT), 256>>>(x, idx, W);
    k2a_stats<<<dim3(NGCH, NBCH), 256>>>();
    k2b_finalize<<<1, GG>>>(gamma, beta, fcw, fcb);
    k3_out<<<BB / 8, 256>>>(out);
}

// round 4
// speedup vs baseline: 2.5969x; 2.5969x over previous
#include <cuda_runtime.h>
#include <math.h>

#define BB 4096
#define GG 512
#define DD 64
#define PP (GG * DD)     // 32768 features per row
#define GPB 16           // groups per k1 block
#define RPB 32           // rows per k1 block
#define NBCH 16          // batch chunks for partial BN stats
#define NGCH 16          // group chunks for partial BN stats

// ---- device scratch (no allocations allowed) ----
__device__ __align__(16) float g_reps[(size_t)BB * GG];   // 8 MiB
__device__ float g_psum[NBCH * GG];
__device__ float g_psq[NBCH * GG];
__device__ __align__(16) float g_c[GG];
__device__ float g_K;

// ---------------------------------------------------------------------------
// k1: reps[b,g] = leaky_relu( sum_d x[b, idx[g,d]] * W[g,d] )
//
// Fast path (idx tile is the identity permutation, true for this dataset):
//   warp w handles groups (g0+2w, g0+2w+1) for 32 rows. One float4 per lane
//   covers both groups (lanes 0-15 -> group 2w, 16-31 -> 2w+1): each warp
//   iteration is ONE perfectly-coalesced 512B LDG.128. Rows unrolled x4 for
//   MLP=4. W held in registers. 4 width-16 shuffles finish each dot.
// Slow path: gathered scalar loads through smem-staged idx (general-correct).
// ---------------------------------------------------------------------------
__global__ __launch_bounds__(256) void k1_reps(const float* __restrict__ x,
                                               const void* __restrict__ idx_raw,
                                               const float* __restrict__ W) {
    __shared__ float sReps[RPB][GPB];          // 2 KiB
    __shared__ int   sIdx[GPB * DD];           // 4 KiB (slow path only)

    const int g0  = blockIdx.x * GPB;
    const int b0  = blockIdx.y * RPB;
    const int tid = threadIdx.x;
    const int w    = tid >> 5;
    const int lane = tid & 31;

    // idx element width: jax x64 -> int64 (high words zero), else int32.
    const int* r32 = (const int*)idx_raw;
    const bool is64 = (r32[1] == 0) && (r32[3] == 0) && (r32[5] == 0);

    // Load this block's idx tile + contiguity check.
    bool ok = true;
    for (int j = tid; j < GPB * DD; j += 256) {
        long long v;
        if (is64) v = ((const long long*)idx_raw)[(size_t)(g0) * DD + j];
        else      v = ((const int*)idx_raw)[(size_t)(g0) * DD + j];
        sIdx[j] = (int)v;
        ok = ok && ((int)v == g0 * DD + j);
    }
    const bool contig = __syncthreads_and(ok);

    const int gpair = g0 + 2 * w;   // first of this warp's two groups
    const int half  = lane >> 4;    // 0 -> group gpair, 1 -> gpair+1
    const int sub   = lane & 15;    // position within the group (x4 floats)

    if (contig) {
        // W for this lane's 4 elements, loaded once, reused for all 32 rows.
        const float4 Wv = ((const float4*)W)[gpair * 16 + lane];
        const float4* xb = (const float4*)x + (size_t)b0 * (PP / 4) + gpair * 16;

        #pragma unroll
        for (int r0 = 0; r0 < RPB; r0 += 4) {
            float4 a[4];
            #pragma unroll
            for (int u = 0; u < 4; u++)
                a[u] = xb[(size_t)(r0 + u) * (PP / 4) + lane];
            #pragma unroll
            for (int u = 0; u < 4; u++) {
                float v = a[u].x * Wv.x + a[u].y * Wv.y
                        + a[u].z * Wv.z + a[u].w * Wv.w;
                v += __shfl_down_sync(0xffffffffu, v, 8, 16);
                v += __shfl_down_sync(0xffffffffu, v, 4, 16);
                v += __shfl_down_sync(0xffffffffu, v, 2, 16);
                v += __shfl_down_sync(0xffffffffu, v, 1, 16);
                if (sub == 0)
                    sReps[r0 + u][2 * w + half] = (v >= 0.0f) ? v : 0.2f * v;
            }
        }
    } else {
        // General gather fallback (same warp->group mapping, scalar loads).
        const int glocal = 2 * w + half;
        float w0 = W[(size_t)(g0 + glocal) * DD + sub * 4 + 0];
        float w1 = W[(size_t)(g0 + glocal) * DD + sub * 4 + 1];
        float w2 = W[(size_t)(g0 + glocal) * DD + sub * 4 + 2];
        float w3 = W[(size_t)(g0 + glocal) * DD + sub * 4 + 3];
        int i0 = sIdx[glocal * DD + sub * 4 + 0];
        int i1 = sIdx[glocal * DD + sub * 4 + 1];
        int i2 = sIdx[glocal * DD + sub * 4 + 2];
        int i3 = sIdx[glocal * DD + sub * 4 + 3];
        for (int r = 0; r < RPB; r++) {
            const float* xrow = x + (size_t)(b0 + r) * PP;
            float v = xrow[i0] * w0 + xrow[i1] * w1 + xrow[i2] * w2 + xrow[i3] * w3;
            v += __shfl_down_sync(0xffffffffu, v, 8, 16);
            v += __shfl_down_sync(0xffffffffu, v, 4, 16);
            v += __shfl_down_sync(0xffffffffu, v, 2, 16);
            v += __shfl_down_sync(0xffffffffu, v, 1, 16);
            if (sub == 0)
                sReps[r][2 * w + half] = (v >= 0.0f) ? v : 0.2f * v;
        }
    }
    __syncthreads();

    // Coalesced write-out: 32 rows x 16 groups.
    #pragma unroll
    for (int j = tid; j < RPB * GPB; j += 256) {
        const int r = j >> 4;
        const int g = j & 15;
        g_reps[(size_t)(b0 + r) * GG + g0 + g] = sReps[r][g];
    }
}

// ---------------------------------------------------------------------------
// k2a: deterministic partial BN stats. Block = (32 groups x 256 rows).
// ---------------------------------------------------------------------------
__global__ __launch_bounds__(256) void k2a_stats() {
    const int g0 = blockIdx.x * 32;
    const int b0 = blockIdx.y * (BB / NBCH);   // 256 rows
    const int tid = threadIdx.x;
    const int gi = tid & 31;
    const int ri = tid >> 5;   // 0..7

    float s = 0.0f, s2 = 0.0f;
    #pragma unroll 4
    for (int i = 0; i < 32; i++) {
        float v = g_reps[(size_t)(b0 + i * 8 + ri) * GG + g0 + gi];
        s += v;
        s2 += v * v;
    }
    __shared__ float shs[8][33];
    __shared__ float shq[8][33];
    shs[ri][gi] = s;
    shq[ri][gi] = s2;
    __syncthreads();
    if (tid < 32) {
        float ts = 0.0f, t2 = 0.0f;
        #pragma unroll
        for (int r = 0; r < 8; r++) { ts += shs[r][tid]; t2 += shq[r][tid]; }
        g_psum[blockIdx.y * GG + g0 + tid] = ts;
        g_psq[blockIdx.y * GG + g0 + tid]  = t2;
    }
}

// ---------------------------------------------------------------------------
// k2b: finalize. c[g] = fc_w*gamma*rstd ; K = fc_b + sum fc_w*(beta - gamma*mean*rstd)
// ---------------------------------------------------------------------------
__global__ __launch_bounds__(GG) void k2b_finalize(const float* __restrict__ gamma,
                                                   const float* __restrict__ beta,
                                                   const float* __restrict__ fcw,
                                                   const float* __restrict__ fcb) {
    const int g = threadIdx.x;
    float s = 0.0f, s2 = 0.0f;
    #pragma unroll
    for (int i = 0; i < NBCH; i++) {
        s  += g_psum[i * GG + g];
        s2 += g_psq[i * GG + g];
    }
    const float inv_b = 1.0f / (float)BB;
    const float mean = s * inv_b;
    const float var = s2 * inv_b - mean * mean;
    const float rstd = rsqrtf(var + 1e-5f);
    const float cg = fcw[g] * gamma[g] * rstd;
    g_c[g] = cg;
    float kterm = fcw[g] * beta[g] - cg * mean;

    __shared__ float sh[GG];
    sh[g] = kterm;
    __syncthreads();
    for (int off = GG / 2; off >= 1; off >>= 1) {
        if (g < off) sh[g] += sh[g + off];
        __syncthreads();
    }
    if (g == 0) g_K = sh[0] + fcb[0];
}

// ---------------------------------------------------------------------------
// k3: out[b] = sigmoid( dot(reps[b,:], c) + K ).  One warp per row, float4.
// ---------------------------------------------------------------------------
__global__ __launch_bounds__(256) void k3_out(float* __restrict__ out) {
    const int gw = (blockIdx.x * blockDim.x + threadIdx.x) >> 5;
    const int lane = threadIdx.x & 31;
    if (gw >= BB) return;

    const float4* row = (const float4*)(g_reps + (size_t)gw * GG);
    const float4* c4 = (const float4*)g_c;
    float acc = 0.0f;
    #pragma unroll
    for (int k = 0; k < 4; k++) {
        float4 a = row[lane + 32 * k];
        float4 b = c4[lane + 32 * k];
        acc += a.x * b.x + a.y * b.y + a.z * b.z + a.w * b.w;
    }
    acc += __shfl_down_sync(0xffffffffu, acc, 16);
    acc += __shfl_down_sync(0xffffffffu, acc, 8);
    acc += __shfl_down_sync(0xffffffffu, acc, 4);
    acc += __shfl_down_sync(0xffffffffu, acc, 2);
    acc += __shfl_down_sync(0xffffffffu, acc, 1);
    if (lane == 0) {
        float l = acc + g_K;
        out[gw] = 1.0f / (1.0f + expf(-l));
    }
}

// ---------------------------------------------------------------------------
extern "C" void kernel_launch(void* const* d_in, const int* in_sizes, int n_in,
                              void* d_out, int out_size) {
    const float* x     = (const float*)d_in[0];
    const void*  idx   = d_in[1];
    const float* W     = (const float*)d_in[2];
    const float* gamma = (const float*)d_in[3];
    const float* beta  = (const float*)d_in[4];
    const float* fcw   = (const float*)d_in[5];
    const float* fcb   = (const float*)d_in[6];
    float* out = (float*)d_out;

    k1_reps<<<dim3(GG / GPB, BB / RPB), 256>>>(x, idx, W);
    k2a_stats<<<dim3(NGCH, NBCH), 256>>>();
    k2b_finalize<<<1, GG>>>(gamma, beta, fcw, fcb);
    k3_out<<<BB / 8, 256>>>(out);
}